// round 14
// baseline (speedup 1.0000x reference)
#include <cuda_runtime.h>

#define HH 128
#define WW 48
#define HW 6144            // 128*48
#define NSPLIT 3
#define MLEN 1920          // 5760 / 3 (split-KV)
#define LOG2E_HALF 0.72134752044448170f   // 0.5*log2(e)

typedef unsigned long long ull;

// ---------------- scratch (device globals) ----------------
__device__ float g_qs[32 * HW];          // q conv output, pre-scaled
__device__ float g_kp[32 * 144 * 64];    // flange-padded k (flat, pad stays 0)
__device__ float g_vp[32 * 144 * 64];    // flange-padded v
__device__ float g_o [32 * HW];          // attention output
__device__ float g_wqkv[3 * 576 * 32];   // repacked [t][pos][co]
__device__ float g_wo[288 * 64];         // repacked [pos][co]
__device__ float g_pnum[NSPLIT * 16 * 4 * 3072];  // partial numerators [s][n][c][q]
__device__ float g_pden[NSPLIT * 16 * 3072];      // partial denominators [s][n][q]

// ---------------- packed f32x2 helpers ----------------
__device__ __forceinline__ ull pk2(float a, float b) {
    ull r; asm("mov.b64 %0,{%1,%2};" : "=l"(r) : "f"(a), "f"(b)); return r;
}
__device__ __forceinline__ void upk2(float& a, float& b, ull v) {
    asm("mov.b64 {%0,%1},%2;" : "=f"(a), "=f"(b) : "l"(v));
}
__device__ __forceinline__ ull fma2(ull a, ull b, ull c) {
    ull d; asm("fma.rn.f32x2 %0,%1,%2,%3;" : "=l"(d) : "l"(a), "l"(b), "l"(c)); return d;
}
__device__ __forceinline__ ull add2(ull a, ull b) {
    ull d; asm("add.rn.f32x2 %0,%1,%2;" : "=l"(d) : "l"(a), "l"(b)); return d;
}
__device__ __forceinline__ ull mul2(ull a, ull b) {
    ull d; asm("mul.rn.f32x2 %0,%1,%2;" : "=l"(d) : "l"(a), "l"(b)); return d;
}
__device__ __forceinline__ float ex2f(float x) {
    float y; asm("ex2.approx.f32 %0, %1;" : "=f"(y) : "f"(x)); return y;
}

// ---------------- weight repack ----------------
__global__ void repack_kernel(const float* __restrict__ wq, const float* __restrict__ wk,
                              const float* __restrict__ wv, const float* __restrict__ wo)
{
    int i = blockIdx.x * blockDim.x + threadIdx.x;
    if (i < 3 * 18432) {
        int t = i / 18432, r = i % 18432;
        int pos = r >> 5, co = r & 31;
        const float* w = (t == 0) ? wq : (t == 1) ? wk : wv;
        g_wqkv[i] = w[co * 576 + pos];
    } else if (i < 3 * 18432 + 18432) {
        int r = i - 3 * 18432;
        int pos = r >> 6, co = r & 63;
        g_wo[r] = wo[co * 288 + pos];
    }
}

// ---------------- QKV conv3x3 (64 -> 32), merged q/k/v, z = co-group of 4 -----------
// grid (3,16,8), 128 threads = 128 px; each thread computes 4 co for ALL of q,k,v.
// sx staged ONCE for the three convs. smem: 11520 + 3*576*4 = 18432 floats = 73.7KB
// -> 3 CTAs/SM, 12 warps/SM.
__global__ __launch_bounds__(128) void conv_qkv_kernel(
    const float* __restrict__ x,
    const float* __restrict__ bq, const float* __restrict__ bk, const float* __restrict__ bv)
{
    extern __shared__ float sm[];
    float* sx = sm;               // 64*10*18 = 11520 floats
    float* sw = sm + 11520;       // [t][576][4] = 6912 floats
    const int z  = blockIdx.z;    // co group of 4
    const int y0 = blockIdx.y * 8, x0 = blockIdx.x * 16;
    const int tid = threadIdx.x;

    for (int idx = tid; idx < 11520; idx += 128) {
        int ci = idx / 180, rem = idx % 180;
        int ry = rem / 18, rx = rem % 18;
        int gy = y0 + ry - 1, gx = x0 + rx - 1;
        float v = 0.f;
        if (gy >= 0 && gy < HH && gx >= 0 && gx < WW) v = x[ci * HW + gy * WW + gx];
        sx[idx] = v;
    }
    for (int idx = tid; idx < 1728; idx += 128) {   // 3t * 576pos, one float4 each
        int t = idx / 576, pos = idx % 576;
        float4 w4 = *(const float4*)(g_wqkv + t * 18432 + pos * 32 + z * 4);
        *(float4*)&sw[t * 2304 + pos * 4] = w4;
    }
    __syncthreads();

    const int ty = tid >> 4, tx = tid & 15;
    const int cobase = z * 4;
    ull aq[2], ak[2], av[2];
    aq[0] = pk2(bq[cobase], bq[cobase+1]); aq[1] = pk2(bq[cobase+2], bq[cobase+3]);
    ak[0] = pk2(bk[cobase], bk[cobase+1]); ak[1] = pk2(bk[cobase+2], bk[cobase+3]);
    av[0] = pk2(bv[cobase], bv[cobase+1]); av[1] = pk2(bv[cobase+2], bv[cobase+3]);

    for (int ci = 0; ci < 64; ci++) {
        #pragma unroll
        for (int ky = 0; ky < 3; ky++) {
            #pragma unroll
            for (int kx = 0; kx < 3; kx++) {
                int pos = ci * 9 + ky * 3 + kx;
                float xv = sx[(ci * 10 + ty + ky) * 18 + tx + kx];
                ull xv2 = pk2(xv, xv);
                ulonglong2 wq_ = *(const ulonglong2*)&sw[pos * 4];
                ulonglong2 wk_ = *(const ulonglong2*)&sw[2304 + pos * 4];
                ulonglong2 wv_ = *(const ulonglong2*)&sw[4608 + pos * 4];
                aq[0] = fma2(xv2, wq_.x, aq[0]); aq[1] = fma2(xv2, wq_.y, aq[1]);
                ak[0] = fma2(xv2, wk_.x, ak[0]); ak[1] = fma2(xv2, wk_.y, ak[1]);
                av[0] = fma2(xv2, wv_.x, av[0]); av[1] = fma2(xv2, wv_.y, av[1]);
            }
        }
    }
    const int y = y0 + ty, xx = x0 + tx;
    float q0,q1,q2,q3, k0,k1,k2,k3, v0,v1,v2,v3;
    upk2(q0,q1,aq[0]); upk2(q2,q3,aq[1]);
    upk2(k0,k1,ak[0]); upk2(k2,k3,ak[1]);
    upk2(v0,v1,av[0]); upk2(v2,v3,av[1]);
    g_qs[(cobase+0)*HW + y*WW + xx] = q0 * LOG2E_HALF;
    g_qs[(cobase+1)*HW + y*WW + xx] = q1 * LOG2E_HALF;
    g_qs[(cobase+2)*HW + y*WW + xx] = q2 * LOG2E_HALF;
    g_qs[(cobase+3)*HW + y*WW + xx] = q3 * LOG2E_HALF;
    g_kp[((cobase+0)*144 + y + 8)*64 + xx + 8] = k0;
    g_kp[((cobase+1)*144 + y + 8)*64 + xx + 8] = k1;
    g_kp[((cobase+2)*144 + y + 8)*64 + xx + 8] = k2;
    g_kp[((cobase+3)*144 + y + 8)*64 + xx + 8] = k3;
    g_vp[((cobase+0)*144 + y + 8)*64 + xx + 8] = v0;
    g_vp[((cobase+1)*144 + y + 8)*64 + xx + 8] = v1;
    g_vp[((cobase+2)*144 + y + 8)*64 + xx + 8] = v2;
    g_vp[((cobase+3)*144 + y + 8)*64 + xx + 8] = v3;
}

// ---------------- block-local attention, 3-way split-KV, MUFU ex2, 256 thr ----------
// grid (6 q-chunks, 16 blocks, 3 kv-thirds); 256 threads x 2 queries = 512 q/CTA.
// smem: component-sliced third-K/V: 8 * 1920 floats = 61440 bytes -> 3 CTAs/SM,
// 24 warps/SM = 6 warps/SMSP for rt-3 banked FFMA2 stall coverage.
__global__ __launch_bounds__(256, 3) void attn_kernel()
{
    extern __shared__ float sk[];
    const int n = blockIdx.y;
    const int s = blockIdx.z;
    const int h = n >> 1, j = n & 1;
    const int tid = threadIdx.x;

    // Stage one third of the flanged K/V (exact as_strided flat map):
    // flat = h*24576 + d*6144 + (s*48 + row)*48 + j*24 + m1
    {
        const int kbase = h * 24576 + j * 24 + s * 2304;
        for (int it = tid; it < MLEN; it += 256) {            // 4 comps * 48 rows * 10 vec4
            int c = it / 480, rem = it % 480;
            int row = rem / 10, v4 = rem % 10;
            int m = row * 40 + v4 * 4;
            int g = kbase + c * 6144 + row * 48 + v4 * 4;
            *(float4*)&sk[c * MLEN + m]          = *(const float4*)&g_kp[g];
            *(float4*)&sk[4*MLEN + c * MLEN + m] = *(const float4*)&g_vp[g];
        }
    }
    __syncthreads();

    const int qA = blockIdx.x * 512 + tid;
    const int qB = qA + 256;
    const int yA = qA / 24, xA = qA - yA * 24;
    const int yB = qB / 24, xB = qB - yB * 24;
    const int aA = yA * WW + j * 24 + xA;
    const int aB = yB * WW + j * 24 + xB;
    const int cb = h * 4 * HW;

    const ull qa0 = pk2(g_qs[cb + aA],        g_qs[cb + aA]);
    const ull qa1 = pk2(g_qs[cb + HW + aA],   g_qs[cb + HW + aA]);
    const ull qa2 = pk2(g_qs[cb + 2*HW + aA], g_qs[cb + 2*HW + aA]);
    const ull qa3 = pk2(g_qs[cb + 3*HW + aA], g_qs[cb + 3*HW + aA]);
    const ull qb0 = pk2(g_qs[cb + aB],        g_qs[cb + aB]);
    const ull qb1 = pk2(g_qs[cb + HW + aB],   g_qs[cb + HW + aB]);
    const ull qb2 = pk2(g_qs[cb + 2*HW + aB], g_qs[cb + 2*HW + aB]);
    const ull qb3 = pk2(g_qs[cb + 3*HW + aB], g_qs[cb + 3*HW + aB]);

    ull denA = 0, aAx = 0, aAy = 0, aAz = 0, aAw = 0;
    ull denB = 0, aBx = 0, aBy = 0, aBz = 0, aBw = 0;

    // 9 FFMA2 on the FMA pipe + 2 ex2 on MUFU per qstep (2 kv elements, 1 query)
    auto qstep = [&](ull q0, ull q1, ull q2, ull q3,
                     ull kx, ull ky, ull kz, ull kw,
                     ull vx, ull vy, ull vz, ull vw,
                     ull& den, ull& ax, ull& ay, ull& az, ull& aw)
    {
        ull s2 = fma2(q3, kw, fma2(q2, kz, fma2(q1, ky, mul2(q0, kx))));
        float sl, sh;
        upk2(sl, sh, s2);                 // free (register-pair aliasing)
        float el = ex2f(sl);              // MUFU
        float eh = ex2f(sh);              // MUFU
        ull e2 = pk2(el, eh);             // free
        den = add2(den, e2);
        ax = fma2(e2, vx, ax); ay = fma2(e2, vy, ay);
        az = fma2(e2, vz, az); aw = fma2(e2, vw, aw);
    };

    const float* skx = sk;
    const float* sky = sk + MLEN;
    const float* skz = sk + 2*MLEN;
    const float* skw = sk + 3*MLEN;
    const float* svx = sk + 4*MLEN;
    const float* svy = sk + 5*MLEN;
    const float* svz = sk + 6*MLEN;
    const float* svw = sk + 7*MLEN;

    for (int m = 0; m < MLEN; m += 4) {
        ulonglong2 kx = *(const ulonglong2*)(skx + m);
        ulonglong2 ky = *(const ulonglong2*)(sky + m);
        ulonglong2 kz = *(const ulonglong2*)(skz + m);
        ulonglong2 kw = *(const ulonglong2*)(skw + m);
        ulonglong2 vx = *(const ulonglong2*)(svx + m);
        ulonglong2 vy = *(const ulonglong2*)(svy + m);
        ulonglong2 vz = *(const ulonglong2*)(svz + m);
        ulonglong2 vw = *(const ulonglong2*)(svw + m);
        qstep(qa0,qa1,qa2,qa3, kx.x,ky.x,kz.x,kw.x, vx.x,vy.x,vz.x,vw.x, denA,aAx,aAy,aAz,aAw);
        qstep(qa0,qa1,qa2,qa3, kx.y,ky.y,kz.y,kw.y, vx.y,vy.y,vz.y,vw.y, denA,aAx,aAy,aAz,aAw);
        qstep(qb0,qb1,qb2,qb3, kx.x,ky.x,kz.x,kw.x, vx.x,vy.x,vz.x,vw.x, denB,aBx,aBy,aBz,aBw);
        qstep(qb0,qb1,qb2,qb3, kx.y,ky.y,kz.y,kw.y, vx.y,vy.y,vz.y,vw.y, denB,aBx,aBy,aBz,aBw);
    }

    float lo, hi;
    const int pbase = (s * 16 + n) * 4 * 3072;
    const int dbase = (s * 16 + n) * 3072;
    upk2(lo, hi, denA); g_pden[dbase + qA] = lo + hi;
    upk2(lo, hi, denB); g_pden[dbase + qB] = lo + hi;
    upk2(lo, hi, aAx); g_pnum[pbase + qA]          = lo + hi;
    upk2(lo, hi, aAy); g_pnum[pbase + 3072 + qA]   = lo + hi;
    upk2(lo, hi, aAz); g_pnum[pbase + 6144 + qA]   = lo + hi;
    upk2(lo, hi, aAw); g_pnum[pbase + 9216 + qA]   = lo + hi;
    upk2(lo, hi, aBx); g_pnum[pbase + qB]          = lo + hi;
    upk2(lo, hi, aBy); g_pnum[pbase + 3072 + qB]   = lo + hi;
    upk2(lo, hi, aBz); g_pnum[pbase + 6144 + qB]   = lo + hi;
    upk2(lo, hi, aBw); g_pnum[pbase + 9216 + qB]   = lo + hi;
}

// ---------------- combine split-KV partials into g_o (float4 per thread) ------------
__global__ __launch_bounds__(128) void combine_kernel()
{
    int idx = blockIdx.x * 128 + threadIdx.x;      // 16*3072/4 = 12288
    int n = idx / 768, rem = idx - n * 768;
    int q = rem * 4;
    int h = n >> 1, j = n & 1;
    int y = q / 24, x = q - y * 24;
    int a = y * WW + j * 24 + x;
    int cb = h * 4 * HW;

    float4 d0 = *(const float4*)&g_pden[n * 3072 + q];
    float4 d1 = *(const float4*)&g_pden[(16 + n) * 3072 + q];
    float4 d2 = *(const float4*)&g_pden[(32 + n) * 3072 + q];
    float4 r;
    r.x = 1.0f / (d0.x + d1.x + d2.x);
    r.y = 1.0f / (d0.y + d1.y + d2.y);
    r.z = 1.0f / (d0.z + d1.z + d2.z);
    r.w = 1.0f / (d0.w + d1.w + d2.w);

    #pragma unroll
    for (int c = 0; c < 4; c++) {
        float4 p0 = *(const float4*)&g_pnum[(n * 4 + c) * 3072 + q];
        float4 p1 = *(const float4*)&g_pnum[((16 + n) * 4 + c) * 3072 + q];
        float4 p2 = *(const float4*)&g_pnum[((32 + n) * 4 + c) * 3072 + q];
        float4 o;
        o.x = (p0.x + p1.x + p2.x) * r.x;
        o.y = (p0.y + p1.y + p2.y) * r.y;
        o.z = (p0.z + p1.z + p2.z) * r.z;
        o.w = (p0.w + p1.w + p2.w) * r.w;
        *(float4*)&g_o[cb + c * HW + a] = o;
    }
}

// ---------------- output conv3x3 (32 -> 64), z = co-group of 8 ----------------------
// grid (3,16,8), 128 threads = 128 px x 8 co. 8-row tiles (kept from R8).
// smem: 5760 + 288*8 = 8064 floats = 32.3KB -> ~2.6 CTAs/SM resident, ~10 warps/SM.
__global__ __launch_bounds__(128) void conv_out_kernel(float* __restrict__ out)
{
    extern __shared__ float sm[];
    float* sx = sm;               // 32*10*18 = 5760 floats
    float* sw = sm + 5760;        // 288*8    = 2304 floats
    const int z  = blockIdx.z;    // co group of 8
    const int y0 = blockIdx.y * 8, x0 = blockIdx.x * 16;
    const int tid = threadIdx.x;

    for (int idx = tid; idx < 5760; idx += 128) {
        int ci = idx / 180, rem = idx % 180;
        int ry = rem / 18, rx = rem % 18;
        int gy = y0 + ry - 1, gx = x0 + rx - 1;
        float v = 0.f;
        if (gy >= 0 && gy < HH && gx >= 0 && gx < WW) v = g_o[ci * HW + gy * WW + gx];
        sx[idx] = v;
    }
    for (int idx = tid; idx < 576; idx += 128) {    // 288 pos x 2 float4
        int pos = idx >> 1, qq = idx & 1;
        float4 w4 = *(const float4*)(g_wo + pos * 64 + z * 8 + qq * 4);
        *(float4*)&sw[pos * 8 + qq * 4] = w4;
    }
    __syncthreads();

    const int ty = tid >> 4, tx = tid & 15;
    ull acc2[4];
    #pragma unroll
    for (int c = 0; c < 4; c++) acc2[c] = 0;

    for (int ci = 0; ci < 32; ci++) {
        #pragma unroll
        for (int ky = 0; ky < 3; ky++) {
            #pragma unroll
            for (int kx = 0; kx < 3; kx++) {
                int pos = ci * 9 + ky * 3 + kx;
                float xv = sx[(ci * 10 + ty + ky) * 18 + tx + kx];
                ull xv2 = pk2(xv, xv);
                const ulonglong2* wr = (const ulonglong2*)&sw[pos * 8];
                ulonglong2 w0 = wr[0];
                ulonglong2 w1 = wr[1];
                acc2[0] = fma2(xv2, w0.x, acc2[0]);
                acc2[1] = fma2(xv2, w0.y, acc2[1]);
                acc2[2] = fma2(xv2, w1.x, acc2[2]);
                acc2[3] = fma2(xv2, w1.y, acc2[3]);
            }
        }
    }
    const int y = y0 + ty, xx = x0 + tx;
    float av[8];
    #pragma unroll
    for (int c = 0; c < 4; c++) upk2(av[2*c], av[2*c+1], acc2[c]);
    #pragma unroll
    for (int c = 0; c < 8; c++)
        out[(z * 8 + c) * HW + y * WW + xx] = av[c];
}

// ---------------- launch ----------------
extern "C" void kernel_launch(void* const* d_in, const int* in_sizes, int n_in,
                              void* d_out, int out_size)
{
    const float* x  = (const float*)d_in[0];
    const float* wq = (const float*)d_in[1];
    const float* bq = (const float*)d_in[2];
    const float* wk = (const float*)d_in[3];
    const float* bk = (const float*)d_in[4];
    const float* wv = (const float*)d_in[5];
    const float* bv = (const float*)d_in[6];
    const float* wo = (const float*)d_in[7];
    float* out = (float*)d_out;

    cudaFuncSetAttribute(conv_qkv_kernel, cudaFuncAttributeMaxDynamicSharedMemorySize, 73728);
    cudaFuncSetAttribute(attn_kernel,     cudaFuncAttributeMaxDynamicSharedMemorySize, 61440);
    cudaFuncSetAttribute(conv_out_kernel, cudaFuncAttributeMaxDynamicSharedMemorySize, 32256);

    repack_kernel<<<(73728 + 255) / 256, 256>>>(wq, wk, wv, wo);
    conv_qkv_kernel<<<dim3(3, 16, 8), 128, 73728>>>(x, bq, bk, bv);
    attn_kernel<<<dim3(6, 16, 3), 256, 61440>>>();
    combine_kernel<<<96, 128>>>();
    conv_out_kernel<<<dim3(3, 16, 8), 128, 32256>>>(out);
}

// round 15
// speedup vs baseline: 1.0223x; 1.0223x over previous
#include <cuda_runtime.h>

#define HH 128
#define WW 48
#define HW 6144            // 128*48
#define NSPLIT 3
#define MLEN 1920          // 5760 / 3 (split-KV)
#define LOG2E_HALF 0.72134752044448170f   // 0.5*log2(e)

typedef unsigned long long ull;

// ---------------- scratch (device globals) ----------------
__device__ float g_qs[32 * HW];          // q conv output, pre-scaled
__device__ float g_kp[32 * 144 * 64];    // flange-padded k (flat, pad stays 0)
__device__ float g_vp[32 * 144 * 64];    // flange-padded v
__device__ float g_o [32 * HW];          // attention output
__device__ float g_wqkv[3 * 576 * 32];   // repacked [t][pos][co]
__device__ float g_wo[288 * 64];         // repacked [pos][co]
__device__ float g_pnum[NSPLIT * 16 * 4 * 3072];  // partial numerators [s][n][c][q]
__device__ float g_pden[NSPLIT * 16 * 3072];      // partial denominators [s][n][q]

// ---------------- packed f32x2 helpers ----------------
__device__ __forceinline__ ull pk2(float a, float b) {
    ull r; asm("mov.b64 %0,{%1,%2};" : "=l"(r) : "f"(a), "f"(b)); return r;
}
__device__ __forceinline__ void upk2(float& a, float& b, ull v) {
    asm("mov.b64 {%0,%1},%2;" : "=f"(a), "=f"(b) : "l"(v));
}
__device__ __forceinline__ ull fma2(ull a, ull b, ull c) {
    ull d; asm("fma.rn.f32x2 %0,%1,%2,%3;" : "=l"(d) : "l"(a), "l"(b), "l"(c)); return d;
}
__device__ __forceinline__ ull add2(ull a, ull b) {
    ull d; asm("add.rn.f32x2 %0,%1,%2;" : "=l"(d) : "l"(a), "l"(b)); return d;
}
__device__ __forceinline__ ull mul2(ull a, ull b) {
    ull d; asm("mul.rn.f32x2 %0,%1,%2;" : "=l"(d) : "l"(a), "l"(b)); return d;
}
__device__ __forceinline__ float ex2f(float x) {
    float y; asm("ex2.approx.f32 %0, %1;" : "=f"(y) : "f"(x)); return y;
}

// ---------------- weight repack ----------------
__global__ void repack_kernel(const float* __restrict__ wq, const float* __restrict__ wk,
                              const float* __restrict__ wv, const float* __restrict__ wo)
{
    int i = blockIdx.x * blockDim.x + threadIdx.x;
    if (i < 3 * 18432) {
        int t = i / 18432, r = i % 18432;
        int pos = r >> 5, co = r & 31;
        const float* w = (t == 0) ? wq : (t == 1) ? wk : wv;
        g_wqkv[i] = w[co * 576 + pos];
    } else if (i < 3 * 18432 + 18432) {
        int r = i - 3 * 18432;
        int pos = r >> 6, co = r & 63;
        g_wo[r] = wo[co * 288 + pos];
    }
}

// ---------------- QKV conv3x3 (64 -> 32), z = t*2 + co-half, packed f32x2 -----------
__global__ __launch_bounds__(128) void conv_qkv_kernel(
    const float* __restrict__ x,
    const float* __restrict__ bq, const float* __restrict__ bk, const float* __restrict__ bv)
{
    extern __shared__ float sm[];
    float* sx = sm;               // 64*10*18 = 11520 floats
    float* sw = sm + 11520;       // 576*16   = 9216 floats
    const int t = blockIdx.z >> 1, half = blockIdx.z & 1;
    const int y0 = blockIdx.y * 8, x0 = blockIdx.x * 16;
    const int tid = threadIdx.x;

    for (int idx = tid; idx < 11520; idx += 128) {
        int ci = idx / 180, rem = idx % 180;
        int ry = rem / 18, rx = rem % 18;
        int gy = y0 + ry - 1, gx = x0 + rx - 1;
        float v = 0.f;
        if (gy >= 0 && gy < HH && gx >= 0 && gx < WW) v = x[ci * HW + gy * WW + gx];
        sx[idx] = v;
    }
    {
        const float* wsrc = g_wqkv + t * 18432 + half * 16;
        for (int idx = tid; idx < 2304; idx += 128) {
            int pos = idx >> 2, q = idx & 3;
            float4 w4 = *(const float4*)(wsrc + pos * 32 + q * 4);
            *(float4*)&sw[pos * 16 + q * 4] = w4;
        }
    }
    __syncthreads();

    const int ty = tid >> 4, tx = tid & 15;
    const float* bias = (t == 0) ? bq : (t == 1) ? bk : bv;
    ull acc2[8];
    #pragma unroll
    for (int c = 0; c < 8; c++) acc2[c] = pk2(bias[half * 16 + 2*c], bias[half * 16 + 2*c + 1]);

    for (int ci = 0; ci < 64; ci++) {
        #pragma unroll
        for (int ky = 0; ky < 3; ky++) {
            #pragma unroll
            for (int kx = 0; kx < 3; kx++) {
                float xv = sx[(ci * 10 + ty + ky) * 18 + tx + kx];
                ull xv2 = pk2(xv, xv);
                const ulonglong2* wr = (const ulonglong2*)&sw[(ci * 9 + ky * 3 + kx) * 16];
                #pragma unroll
                for (int jj = 0; jj < 4; jj++) {
                    ulonglong2 w = wr[jj];
                    acc2[2*jj]   = fma2(xv2, w.x, acc2[2*jj]);
                    acc2[2*jj+1] = fma2(xv2, w.y, acc2[2*jj+1]);
                }
            }
        }
    }
    const int y = y0 + ty, xx = x0 + tx;
    float av[16];
    #pragma unroll
    for (int c = 0; c < 8; c++) upk2(av[2*c], av[2*c+1], acc2[c]);
    if (t == 0) {
        #pragma unroll
        for (int c = 0; c < 16; c++)
            g_qs[(half * 16 + c) * HW + y * WW + xx] = av[c] * LOG2E_HALF;
    } else {
        float* dst = (t == 1) ? g_kp : g_vp;
        #pragma unroll
        for (int c = 0; c < 16; c++)
            dst[((half * 16 + c) * 144 + y + 8) * 64 + (xx + 8)] = av[c];
    }
}

// ---------------- block-local attention, 3-way split-KV, MUFU ex2, 256 thr ----------
// grid (6 q-chunks, 16 blocks, 3 kv-thirds); 256 threads x 2 queries = 512 q/CTA.
// smem: component-sliced third-K/V: 8 * 1920 floats = 61440 bytes -> 3 CTAs/SM,
// 24 warps/SM = 6 warps/SMSP for rt-3 banked FFMA2 stall coverage.
__global__ __launch_bounds__(256, 3) void attn_kernel()
{
    extern __shared__ float sk[];
    const int n = blockIdx.y;
    const int s = blockIdx.z;
    const int h = n >> 1, j = n & 1;
    const int tid = threadIdx.x;

    // Stage one third of the flanged K/V (exact as_strided flat map):
    // flat = h*24576 + d*6144 + (s*48 + row)*48 + j*24 + m1
    {
        const int kbase = h * 24576 + j * 24 + s * 2304;
        for (int it = tid; it < MLEN; it += 256) {            // 4 comps * 48 rows * 10 vec4
            int c = it / 480, rem = it % 480;
            int row = rem / 10, v4 = rem % 10;
            int m = row * 40 + v4 * 4;
            int g = kbase + c * 6144 + row * 48 + v4 * 4;
            *(float4*)&sk[c * MLEN + m]          = *(const float4*)&g_kp[g];
            *(float4*)&sk[4*MLEN + c * MLEN + m] = *(const float4*)&g_vp[g];
        }
    }
    __syncthreads();

    const int qA = blockIdx.x * 512 + tid;
    const int qB = qA + 256;
    const int yA = qA / 24, xA = qA - yA * 24;
    const int yB = qB / 24, xB = qB - yB * 24;
    const int aA = yA * WW + j * 24 + xA;
    const int aB = yB * WW + j * 24 + xB;
    const int cb = h * 4 * HW;

    const ull qa0 = pk2(g_qs[cb + aA],        g_qs[cb + aA]);
    const ull qa1 = pk2(g_qs[cb + HW + aA],   g_qs[cb + HW + aA]);
    const ull qa2 = pk2(g_qs[cb + 2*HW + aA], g_qs[cb + 2*HW + aA]);
    const ull qa3 = pk2(g_qs[cb + 3*HW + aA], g_qs[cb + 3*HW + aA]);
    const ull qb0 = pk2(g_qs[cb + aB],        g_qs[cb + aB]);
    const ull qb1 = pk2(g_qs[cb + HW + aB],   g_qs[cb + HW + aB]);
    const ull qb2 = pk2(g_qs[cb + 2*HW + aB], g_qs[cb + 2*HW + aB]);
    const ull qb3 = pk2(g_qs[cb + 3*HW + aB], g_qs[cb + 3*HW + aB]);

    ull denA = 0, aAx = 0, aAy = 0, aAz = 0, aAw = 0;
    ull denB = 0, aBx = 0, aBy = 0, aBz = 0, aBw = 0;

    // 9 FFMA2 on the FMA pipe + 2 ex2 on MUFU per qstep (2 kv elements, 1 query)
    auto qstep = [&](ull q0, ull q1, ull q2, ull q3,
                     ull kx, ull ky, ull kz, ull kw,
                     ull vx, ull vy, ull vz, ull vw,
                     ull& den, ull& ax, ull& ay, ull& az, ull& aw)
    {
        ull s2 = fma2(q3, kw, fma2(q2, kz, fma2(q1, ky, mul2(q0, kx))));
        float sl, sh;
        upk2(sl, sh, s2);                 // free (register-pair aliasing)
        float el = ex2f(sl);              // MUFU
        float eh = ex2f(sh);              // MUFU
        ull e2 = pk2(el, eh);             // free
        den = add2(den, e2);
        ax = fma2(e2, vx, ax); ay = fma2(e2, vy, ay);
        az = fma2(e2, vz, az); aw = fma2(e2, vw, aw);
    };

    const float* skx = sk;
    const float* sky = sk + MLEN;
    const float* skz = sk + 2*MLEN;
    const float* skw = sk + 3*MLEN;
    const float* svx = sk + 4*MLEN;
    const float* svy = sk + 5*MLEN;
    const float* svz = sk + 6*MLEN;
    const float* svw = sk + 7*MLEN;

    for (int m = 0; m < MLEN; m += 4) {
        ulonglong2 kx = *(const ulonglong2*)(skx + m);
        ulonglong2 ky = *(const ulonglong2*)(sky + m);
        ulonglong2 kz = *(const ulonglong2*)(skz + m);
        ulonglong2 kw = *(const ulonglong2*)(skw + m);
        ulonglong2 vx = *(const ulonglong2*)(svx + m);
        ulonglong2 vy = *(const ulonglong2*)(svy + m);
        ulonglong2 vz = *(const ulonglong2*)(svz + m);
        ulonglong2 vw = *(const ulonglong2*)(svw + m);
        qstep(qa0,qa1,qa2,qa3, kx.x,ky.x,kz.x,kw.x, vx.x,vy.x,vz.x,vw.x, denA,aAx,aAy,aAz,aAw);
        qstep(qa0,qa1,qa2,qa3, kx.y,ky.y,kz.y,kw.y, vx.y,vy.y,vz.y,vw.y, denA,aAx,aAy,aAz,aAw);
        qstep(qb0,qb1,qb2,qb3, kx.x,ky.x,kz.x,kw.x, vx.x,vy.x,vz.x,vw.x, denB,aBx,aBy,aBz,aBw);
        qstep(qb0,qb1,qb2,qb3, kx.y,ky.y,kz.y,kw.y, vx.y,vy.y,vz.y,vw.y, denB,aBx,aBy,aBz,aBw);
    }

    float lo, hi;
    const int pbase = (s * 16 + n) * 4 * 3072;
    const int dbase = (s * 16 + n) * 3072;
    upk2(lo, hi, denA); g_pden[dbase + qA] = lo + hi;
    upk2(lo, hi, denB); g_pden[dbase + qB] = lo + hi;
    upk2(lo, hi, aAx); g_pnum[pbase + qA]          = lo + hi;
    upk2(lo, hi, aAy); g_pnum[pbase + 3072 + qA]   = lo + hi;
    upk2(lo, hi, aAz); g_pnum[pbase + 6144 + qA]   = lo + hi;
    upk2(lo, hi, aAw); g_pnum[pbase + 9216 + qA]   = lo + hi;
    upk2(lo, hi, aBx); g_pnum[pbase + qB]          = lo + hi;
    upk2(lo, hi, aBy); g_pnum[pbase + 3072 + qB]   = lo + hi;
    upk2(lo, hi, aBz); g_pnum[pbase + 6144 + qB]   = lo + hi;
    upk2(lo, hi, aBw); g_pnum[pbase + 9216 + qB]   = lo + hi;
}

// ---------------- combine split-KV partials into g_o --------------------------------
// Fine-grained: one thread per (n, c, q-quad) = 49152 threads (4x R8) for
// DRAM-latency hiding; den re-read per c is L2-hot, extra traffic ~1.8MB.
__global__ __launch_bounds__(128) void combine_kernel()
{
    int idx = blockIdx.x * 128 + threadIdx.x;      // 16*4*768 = 49152
    int n = idx / 3072, rem = idx - n * 3072;
    int c = rem / 768;
    int q = (rem - c * 768) * 4;
    int h = n >> 1, j = n & 1;
    int y = q / 24, x = q - y * 24;
    int a = y * WW + j * 24 + x;
    int cb = h * 4 * HW;

    float4 d0 = *(const float4*)&g_pden[n * 3072 + q];
    float4 d1 = *(const float4*)&g_pden[(16 + n) * 3072 + q];
    float4 d2 = *(const float4*)&g_pden[(32 + n) * 3072 + q];
    float4 p0 = *(const float4*)&g_pnum[(n * 4 + c) * 3072 + q];
    float4 p1 = *(const float4*)&g_pnum[((16 + n) * 4 + c) * 3072 + q];
    float4 p2 = *(const float4*)&g_pnum[((32 + n) * 4 + c) * 3072 + q];
    float4 o;
    o.x = (p0.x + p1.x + p2.x) / (d0.x + d1.x + d2.x);
    o.y = (p0.y + p1.y + p2.y) / (d0.y + d1.y + d2.y);
    o.z = (p0.z + p1.z + p2.z) / (d0.z + d1.z + d2.z);
    o.w = (p0.w + p1.w + p2.w) / (d0.w + d1.w + d2.w);
    *(float4*)&g_o[cb + c * HW + a] = o;
}

// ---------------- output conv3x3 (32 -> 64), z = co quarter, packed f32x2 -----------
__global__ __launch_bounds__(128) void conv_out_kernel(float* __restrict__ out)
{
    extern __shared__ float sm[];
    float* sx = sm;               // 32*10*18 = 5760 floats
    float* sw = sm + 5760;        // 288*16   = 4608 floats
    const int z  = blockIdx.z;
    const int y0 = blockIdx.y * 8, x0 = blockIdx.x * 16;
    const int tid = threadIdx.x;

    for (int idx = tid; idx < 5760; idx += 128) {
        int ci = idx / 180, rem = idx % 180;
        int ry = rem / 18, rx = rem % 18;
        int gy = y0 + ry - 1, gx = x0 + rx - 1;
        float v = 0.f;
        if (gy >= 0 && gy < HH && gx >= 0 && gx < WW) v = g_o[ci * HW + gy * WW + gx];
        sx[idx] = v;
    }
    for (int idx = tid; idx < 1152; idx += 128) {
        int pos = idx >> 2, q = idx & 3;
        float4 w4 = *(const float4*)(g_wo + pos * 64 + z * 16 + q * 4);
        *(float4*)&sw[pos * 16 + q * 4] = w4;
    }
    __syncthreads();

    const int ty = tid >> 4, tx = tid & 15;
    ull acc2[8];
    #pragma unroll
    for (int c = 0; c < 8; c++) acc2[c] = 0;

    for (int ci = 0; ci < 32; ci++) {
        #pragma unroll
        for (int ky = 0; ky < 3; ky++) {
            #pragma unroll
            for (int kx = 0; kx < 3; kx++) {
                float xv = sx[(ci * 10 + ty + ky) * 18 + tx + kx];
                ull xv2 = pk2(xv, xv);
                const ulonglong2* wr = (const ulonglong2*)&sw[(ci * 9 + ky * 3 + kx) * 16];
                #pragma unroll
                for (int jj = 0; jj < 4; jj++) {
                    ulonglong2 w = wr[jj];
                    acc2[2*jj]   = fma2(xv2, w.x, acc2[2*jj]);
                    acc2[2*jj+1] = fma2(xv2, w.y, acc2[2*jj+1]);
                }
            }
        }
    }
    const int y = y0 + ty, xx = x0 + tx;
    float av[16];
    #pragma unroll
    for (int c = 0; c < 8; c++) upk2(av[2*c], av[2*c+1], acc2[c]);
    #pragma unroll
    for (int c = 0; c < 16; c++)
        out[(z * 16 + c) * HW + y * WW + xx] = av[c];
}

// ---------------- launch ----------------
extern "C" void kernel_launch(void* const* d_in, const int* in_sizes, int n_in,
                              void* d_out, int out_size)
{
    const float* x  = (const float*)d_in[0];
    const float* wq = (const float*)d_in[1];
    const float* bq = (const float*)d_in[2];
    const float* wk = (const float*)d_in[3];
    const float* bk = (const float*)d_in[4];
    const float* wv = (const float*)d_in[5];
    const float* bv = (const float*)d_in[6];
    const float* wo = (const float*)d_in[7];
    float* out = (float*)d_out;

    cudaFuncSetAttribute(conv_qkv_kernel, cudaFuncAttributeMaxDynamicSharedMemorySize, 82944);
    cudaFuncSetAttribute(attn_kernel,     cudaFuncAttributeMaxDynamicSharedMemorySize, 61440);
    cudaFuncSetAttribute(conv_out_kernel, cudaFuncAttributeMaxDynamicSharedMemorySize, 41472);

    repack_kernel<<<(73728 + 255) / 256, 256>>>(wq, wk, wv, wo);
    conv_qkv_kernel<<<dim3(3, 16, 6), 128, 82944>>>(x, bq, bk, bv);
    attn_kernel<<<dim3(6, 16, 3), 256, 61440>>>();
    combine_kernel<<<384, 128>>>();
    conv_out_kernel<<<dim3(3, 16, 4), 128, 41472>>>(out);
}

// round 16
// speedup vs baseline: 1.0237x; 1.0014x over previous
#include <cuda_runtime.h>

#define HH 128
#define WW 48
#define HW 6144            // 128*48
#define NSPLIT 3
#define MLEN 1920          // 5760 / 3 (split-KV)
#define LOG2E_HALF 0.72134752044448170f   // 0.5*log2(e)

typedef unsigned long long ull;

// ---------------- scratch (device globals) ----------------
__device__ float g_qs[32 * HW];          // q conv output, pre-scaled
__device__ float g_kp[32 * 144 * 64];    // flange-padded k (flat, pad stays 0)
__device__ float g_vp[32 * 144 * 64];    // flange-padded v
__device__ float g_o [32 * HW];          // attention output
__device__ float g_wqkv[3 * 576 * 32];   // repacked [t][pos][co]
__device__ float g_wo[288 * 64];         // repacked [pos][co]
__device__ float g_pnum[NSPLIT * 16 * 4 * 3072];  // partial numerators [s][n][c][q]
__device__ float g_pden[NSPLIT * 16 * 3072];      // partial denominators [s][n][q]

// ---------------- packed f32x2 helpers ----------------
__device__ __forceinline__ ull pk2(float a, float b) {
    ull r; asm("mov.b64 %0,{%1,%2};" : "=l"(r) : "f"(a), "f"(b)); return r;
}
__device__ __forceinline__ void upk2(float& a, float& b, ull v) {
    asm("mov.b64 {%0,%1},%2;" : "=f"(a), "=f"(b) : "l"(v));
}
__device__ __forceinline__ ull fma2(ull a, ull b, ull c) {
    ull d; asm("fma.rn.f32x2 %0,%1,%2,%3;" : "=l"(d) : "l"(a), "l"(b), "l"(c)); return d;
}
__device__ __forceinline__ ull add2(ull a, ull b) {
    ull d; asm("add.rn.f32x2 %0,%1,%2;" : "=l"(d) : "l"(a), "l"(b)); return d;
}
__device__ __forceinline__ ull mul2(ull a, ull b) {
    ull d; asm("mul.rn.f32x2 %0,%1,%2;" : "=l"(d) : "l"(a), "l"(b)); return d;
}
__device__ __forceinline__ float ex2f(float x) {
    float y; asm("ex2.approx.f32 %0, %1;" : "=f"(y) : "f"(x)); return y;
}

// ---------------- weight repack ----------------
__global__ void repack_kernel(const float* __restrict__ wq, const float* __restrict__ wk,
                              const float* __restrict__ wv, const float* __restrict__ wo)
{
    int i = blockIdx.x * blockDim.x + threadIdx.x;
    if (i < 3 * 18432) {
        int t = i / 18432, r = i % 18432;
        int pos = r >> 5, co = r & 31;
        const float* w = (t == 0) ? wq : (t == 1) ? wk : wv;
        g_wqkv[i] = w[co * 576 + pos];
    } else if (i < 3 * 18432 + 18432) {
        int r = i - 3 * 18432;
        int pos = r >> 6, co = r & 63;
        g_wo[r] = wo[co * 288 + pos];
    }
}

// ---------------- QKV conv3x3 (64 -> 32), z = t*2 + co-half, packed f32x2 -----------
__global__ __launch_bounds__(128) void conv_qkv_kernel(
    const float* __restrict__ x,
    const float* __restrict__ bq, const float* __restrict__ bk, const float* __restrict__ bv)
{
    extern __shared__ float sm[];
    float* sx = sm;               // 64*10*18 = 11520 floats
    float* sw = sm + 11520;       // 576*16   = 9216 floats
    const int t = blockIdx.z >> 1, half = blockIdx.z & 1;
    const int y0 = blockIdx.y * 8, x0 = blockIdx.x * 16;
    const int tid = threadIdx.x;

    for (int idx = tid; idx < 11520; idx += 128) {
        int ci = idx / 180, rem = idx % 180;
        int ry = rem / 18, rx = rem % 18;
        int gy = y0 + ry - 1, gx = x0 + rx - 1;
        float v = 0.f;
        if (gy >= 0 && gy < HH && gx >= 0 && gx < WW) v = x[ci * HW + gy * WW + gx];
        sx[idx] = v;
    }
    {
        const float* wsrc = g_wqkv + t * 18432 + half * 16;
        for (int idx = tid; idx < 2304; idx += 128) {
            int pos = idx >> 2, q = idx & 3;
            float4 w4 = *(const float4*)(wsrc + pos * 32 + q * 4);
            *(float4*)&sw[pos * 16 + q * 4] = w4;
        }
    }
    __syncthreads();

    const int ty = tid >> 4, tx = tid & 15;
    const float* bias = (t == 0) ? bq : (t == 1) ? bk : bv;
    ull acc2[8];
    #pragma unroll
    for (int c = 0; c < 8; c++) acc2[c] = pk2(bias[half * 16 + 2*c], bias[half * 16 + 2*c + 1]);

    for (int ci = 0; ci < 64; ci++) {
        #pragma unroll
        for (int ky = 0; ky < 3; ky++) {
            #pragma unroll
            for (int kx = 0; kx < 3; kx++) {
                float xv = sx[(ci * 10 + ty + ky) * 18 + tx + kx];
                ull xv2 = pk2(xv, xv);
                const ulonglong2* wr = (const ulonglong2*)&sw[(ci * 9 + ky * 3 + kx) * 16];
                #pragma unroll
                for (int jj = 0; jj < 4; jj++) {
                    ulonglong2 w = wr[jj];
                    acc2[2*jj]   = fma2(xv2, w.x, acc2[2*jj]);
                    acc2[2*jj+1] = fma2(xv2, w.y, acc2[2*jj+1]);
                }
            }
        }
    }
    const int y = y0 + ty, xx = x0 + tx;
    float av[16];
    #pragma unroll
    for (int c = 0; c < 8; c++) upk2(av[2*c], av[2*c+1], acc2[c]);
    if (t == 0) {
        #pragma unroll
        for (int c = 0; c < 16; c++)
            g_qs[(half * 16 + c) * HW + y * WW + xx] = av[c] * LOG2E_HALF;
    } else {
        float* dst = (t == 1) ? g_kp : g_vp;
        #pragma unroll
        for (int c = 0; c < 16; c++)
            dst[((half * 16 + c) * 144 + y + 8) * 64 + (xx + 8)] = av[c];
    }
}

// ---------------- block-local attention, 3-way split-KV, MUFU ex2, 256 thr ----------
// grid (6 q-chunks, 16 blocks, 3 kv-thirds); 256 threads x 2 queries = 512 q/CTA.
// smem: component-sliced third-K/V: 8 * 1920 floats = 61440 bytes -> 3 CTAs/SM,
// 24 warps/SM = 6 warps/SMSP for rt-3 banked FFMA2 stall coverage.
__global__ __launch_bounds__(256, 3) void attn_kernel()
{
    extern __shared__ float sk[];
    const int n = blockIdx.y;
    const int s = blockIdx.z;
    const int h = n >> 1, j = n & 1;
    const int tid = threadIdx.x;

    // Stage one third of the flanged K/V (exact as_strided flat map):
    // flat = h*24576 + d*6144 + (s*48 + row)*48 + j*24 + m1
    {
        const int kbase = h * 24576 + j * 24 + s * 2304;
        for (int it = tid; it < MLEN; it += 256) {            // 4 comps * 48 rows * 10 vec4
            int c = it / 480, rem = it % 480;
            int row = rem / 10, v4 = rem % 10;
            int m = row * 40 + v4 * 4;
            int g = kbase + c * 6144 + row * 48 + v4 * 4;
            *(float4*)&sk[c * MLEN + m]          = *(const float4*)&g_kp[g];
            *(float4*)&sk[4*MLEN + c * MLEN + m] = *(const float4*)&g_vp[g];
        }
    }
    __syncthreads();

    const int qA = blockIdx.x * 512 + tid;
    const int qB = qA + 256;
    const int yA = qA / 24, xA = qA - yA * 24;
    const int yB = qB / 24, xB = qB - yB * 24;
    const int aA = yA * WW + j * 24 + xA;
    const int aB = yB * WW + j * 24 + xB;
    const int cb = h * 4 * HW;

    const ull qa0 = pk2(g_qs[cb + aA],        g_qs[cb + aA]);
    const ull qa1 = pk2(g_qs[cb + HW + aA],   g_qs[cb + HW + aA]);
    const ull qa2 = pk2(g_qs[cb + 2*HW + aA], g_qs[cb + 2*HW + aA]);
    const ull qa3 = pk2(g_qs[cb + 3*HW + aA], g_qs[cb + 3*HW + aA]);
    const ull qb0 = pk2(g_qs[cb + aB],        g_qs[cb + aB]);
    const ull qb1 = pk2(g_qs[cb + HW + aB],   g_qs[cb + HW + aB]);
    const ull qb2 = pk2(g_qs[cb + 2*HW + aB], g_qs[cb + 2*HW + aB]);
    const ull qb3 = pk2(g_qs[cb + 3*HW + aB], g_qs[cb + 3*HW + aB]);

    ull denA = 0, aAx = 0, aAy = 0, aAz = 0, aAw = 0;
    ull denB = 0, aBx = 0, aBy = 0, aBz = 0, aBw = 0;

    // 9 FFMA2 on the FMA pipe + 2 ex2 on MUFU per qstep (2 kv elements, 1 query)
    auto qstep = [&](ull q0, ull q1, ull q2, ull q3,
                     ull kx, ull ky, ull kz, ull kw,
                     ull vx, ull vy, ull vz, ull vw,
                     ull& den, ull& ax, ull& ay, ull& az, ull& aw)
    {
        ull s2 = fma2(q3, kw, fma2(q2, kz, fma2(q1, ky, mul2(q0, kx))));
        float sl, sh;
        upk2(sl, sh, s2);                 // free (register-pair aliasing)
        float el = ex2f(sl);              // MUFU
        float eh = ex2f(sh);              // MUFU
        ull e2 = pk2(el, eh);             // free
        den = add2(den, e2);
        ax = fma2(e2, vx, ax); ay = fma2(e2, vy, ay);
        az = fma2(e2, vz, az); aw = fma2(e2, vw, aw);
    };

    const float* skx = sk;
    const float* sky = sk + MLEN;
    const float* skz = sk + 2*MLEN;
    const float* skw = sk + 3*MLEN;
    const float* svx = sk + 4*MLEN;
    const float* svy = sk + 5*MLEN;
    const float* svz = sk + 6*MLEN;
    const float* svw = sk + 7*MLEN;

    for (int m = 0; m < MLEN; m += 4) {
        ulonglong2 kx = *(const ulonglong2*)(skx + m);
        ulonglong2 ky = *(const ulonglong2*)(sky + m);
        ulonglong2 kz = *(const ulonglong2*)(skz + m);
        ulonglong2 kw = *(const ulonglong2*)(skw + m);
        ulonglong2 vx = *(const ulonglong2*)(svx + m);
        ulonglong2 vy = *(const ulonglong2*)(svy + m);
        ulonglong2 vz = *(const ulonglong2*)(svz + m);
        ulonglong2 vw = *(const ulonglong2*)(svw + m);
        qstep(qa0,qa1,qa2,qa3, kx.x,ky.x,kz.x,kw.x, vx.x,vy.x,vz.x,vw.x, denA,aAx,aAy,aAz,aAw);
        qstep(qa0,qa1,qa2,qa3, kx.y,ky.y,kz.y,kw.y, vx.y,vy.y,vz.y,vw.y, denA,aAx,aAy,aAz,aAw);
        qstep(qb0,qb1,qb2,qb3, kx.x,ky.x,kz.x,kw.x, vx.x,vy.x,vz.x,vw.x, denB,aBx,aBy,aBz,aBw);
        qstep(qb0,qb1,qb2,qb3, kx.y,ky.y,kz.y,kw.y, vx.y,vy.y,vz.y,vw.y, denB,aBx,aBy,aBz,aBw);
    }

    float lo, hi;
    const int pbase = (s * 16 + n) * 4 * 3072;
    const int dbase = (s * 16 + n) * 3072;
    upk2(lo, hi, denA); g_pden[dbase + qA] = lo + hi;
    upk2(lo, hi, denB); g_pden[dbase + qB] = lo + hi;
    upk2(lo, hi, aAx); g_pnum[pbase + qA]          = lo + hi;
    upk2(lo, hi, aAy); g_pnum[pbase + 3072 + qA]   = lo + hi;
    upk2(lo, hi, aAz); g_pnum[pbase + 6144 + qA]   = lo + hi;
    upk2(lo, hi, aAw); g_pnum[pbase + 9216 + qA]   = lo + hi;
    upk2(lo, hi, aBx); g_pnum[pbase + qB]          = lo + hi;
    upk2(lo, hi, aBy); g_pnum[pbase + 3072 + qB]   = lo + hi;
    upk2(lo, hi, aBz); g_pnum[pbase + 6144 + qB]   = lo + hi;
    upk2(lo, hi, aBw); g_pnum[pbase + 9216 + qB]   = lo + hi;
}

// ---------------- combine split-KV partials into g_o --------------------------------
// Fine-grained: one thread per (n, c, q-quad) = 49152 threads (4x R8) for
// DRAM-latency hiding; den re-read per c is L2-hot, extra traffic ~1.8MB.
__global__ __launch_bounds__(128) void combine_kernel()
{
    int idx = blockIdx.x * 128 + threadIdx.x;      // 16*4*768 = 49152
    int n = idx / 3072, rem = idx - n * 3072;
    int c = rem / 768;
    int q = (rem - c * 768) * 4;
    int h = n >> 1, j = n & 1;
    int y = q / 24, x = q - y * 24;
    int a = y * WW + j * 24 + x;
    int cb = h * 4 * HW;

    float4 d0 = *(const float4*)&g_pden[n * 3072 + q];
    float4 d1 = *(const float4*)&g_pden[(16 + n) * 3072 + q];
    float4 d2 = *(const float4*)&g_pden[(32 + n) * 3072 + q];
    float4 p0 = *(const float4*)&g_pnum[(n * 4 + c) * 3072 + q];
    float4 p1 = *(const float4*)&g_pnum[((16 + n) * 4 + c) * 3072 + q];
    float4 p2 = *(const float4*)&g_pnum[((32 + n) * 4 + c) * 3072 + q];
    float4 o;
    o.x = (p0.x + p1.x + p2.x) / (d0.x + d1.x + d2.x);
    o.y = (p0.y + p1.y + p2.y) / (d0.y + d1.y + d2.y);
    o.z = (p0.z + p1.z + p2.z) / (d0.z + d1.z + d2.z);
    o.w = (p0.w + p1.w + p2.w) / (d0.w + d1.w + d2.w);
    *(float4*)&g_o[cb + c * HW + a] = o;
}

// ---------------- output conv3x3 (32 -> 64), z = co quarter, packed f32x2 -----------
__global__ __launch_bounds__(128) void conv_out_kernel(float* __restrict__ out)
{
    extern __shared__ float sm[];
    float* sx = sm;               // 32*10*18 = 5760 floats
    float* sw = sm + 5760;        // 288*16   = 4608 floats
    const int z  = blockIdx.z;
    const int y0 = blockIdx.y * 8, x0 = blockIdx.x * 16;
    const int tid = threadIdx.x;

    for (int idx = tid; idx < 5760; idx += 128) {
        int ci = idx / 180, rem = idx % 180;
        int ry = rem / 18, rx = rem % 18;
        int gy = y0 + ry - 1, gx = x0 + rx - 1;
        float v = 0.f;
        if (gy >= 0 && gy < HH && gx >= 0 && gx < WW) v = g_o[ci * HW + gy * WW + gx];
        sx[idx] = v;
    }
    for (int idx = tid; idx < 1152; idx += 128) {
        int pos = idx >> 2, q = idx & 3;
        float4 w4 = *(const float4*)(g_wo + pos * 64 + z * 16 + q * 4);
        *(float4*)&sw[pos * 16 + q * 4] = w4;
    }
    __syncthreads();

    const int ty = tid >> 4, tx = tid & 15;
    ull acc2[8];
    #pragma unroll
    for (int c = 0; c < 8; c++) acc2[c] = 0;

    for (int ci = 0; ci < 32; ci++) {
        #pragma unroll
        for (int ky = 0; ky < 3; ky++) {
            #pragma unroll
            for (int kx = 0; kx < 3; kx++) {
                float xv = sx[(ci * 10 + ty + ky) * 18 + tx + kx];
                ull xv2 = pk2(xv, xv);
                const ulonglong2* wr = (const ulonglong2*)&sw[(ci * 9 + ky * 3 + kx) * 16];
                #pragma unroll
                for (int jj = 0; jj < 4; jj++) {
                    ulonglong2 w = wr[jj];
                    acc2[2*jj]   = fma2(xv2, w.x, acc2[2*jj]);
                    acc2[2*jj+1] = fma2(xv2, w.y, acc2[2*jj+1]);
                }
            }
        }
    }
    const int y = y0 + ty, xx = x0 + tx;
    float av[16];
    #pragma unroll
    for (int c = 0; c < 8; c++) upk2(av[2*c], av[2*c+1], acc2[c]);
    #pragma unroll
    for (int c = 0; c < 16; c++)
        out[(z * 16 + c) * HW + y * WW + xx] = av[c];
}

// ---------------- launch ----------------
extern "C" void kernel_launch(void* const* d_in, const int* in_sizes, int n_in,
                              void* d_out, int out_size)
{
    const float* x  = (const float*)d_in[0];
    const float* wq = (const float*)d_in[1];
    const float* bq = (const float*)d_in[2];
    const float* wk = (const float*)d_in[3];
    const float* bk = (const float*)d_in[4];
    const float* wv = (const float*)d_in[5];
    const float* bv = (const float*)d_in[6];
    const float* wo = (const float*)d_in[7];
    float* out = (float*)d_out;

    cudaFuncSetAttribute(conv_qkv_kernel, cudaFuncAttributeMaxDynamicSharedMemorySize, 82944);
    cudaFuncSetAttribute(attn_kernel,     cudaFuncAttributeMaxDynamicSharedMemorySize, 61440);
    cudaFuncSetAttribute(conv_out_kernel, cudaFuncAttributeMaxDynamicSharedMemorySize, 41472);

    repack_kernel<<<(73728 + 255) / 256, 256>>>(wq, wk, wv, wo);
    conv_qkv_kernel<<<dim3(3, 16, 6), 128, 82944>>>(x, bq, bk, bv);
    attn_kernel<<<dim3(6, 16, 3), 256, 61440>>>();
    combine_kernel<<<384, 128>>>();
    conv_out_kernel<<<dim3(3, 16, 4), 128, 41472>>>(out);
}

// round 17
// speedup vs baseline: 1.0284x; 1.0045x over previous
#include <cuda_runtime.h>

#define HH 128
#define WW 48
#define HW 6144            // 128*48
#define NSPLIT 3
#define MLEN 1920          // 5760 / 3 (split-KV)
#define LOG2E_HALF 0.72134752044448170f   // 0.5*log2(e)

typedef unsigned long long ull;

// ---------------- scratch (device globals) ----------------
__device__ float g_qs[32 * HW];          // q conv output, pre-scaled
__device__ float g_kp[32 * 144 * 64];    // flange-padded k (flat, pad stays 0)
__device__ float g_vp[32 * 144 * 64];    // flange-padded v
__device__ float g_o [32 * HW];          // attention output
__device__ float g_wqkv[3 * 576 * 32];   // repacked [t][pos][co]
__device__ float g_wo[288 * 64];         // repacked [pos][co]
__device__ float g_pnum[NSPLIT * 16 * 4 * 3072];  // partial numerators [s][n][c][q]
__device__ float g_pden[NSPLIT * 16 * 3072];      // partial denominators [s][n][q]

// ---------------- packed f32x2 helpers ----------------
__device__ __forceinline__ ull pk2(float a, float b) {
    ull r; asm("mov.b64 %0,{%1,%2};" : "=l"(r) : "f"(a), "f"(b)); return r;
}
__device__ __forceinline__ void upk2(float& a, float& b, ull v) {
    asm("mov.b64 {%0,%1},%2;" : "=f"(a), "=f"(b) : "l"(v));
}
__device__ __forceinline__ ull fma2(ull a, ull b, ull c) {
    ull d; asm("fma.rn.f32x2 %0,%1,%2,%3;" : "=l"(d) : "l"(a), "l"(b), "l"(c)); return d;
}
__device__ __forceinline__ ull add2(ull a, ull b) {
    ull d; asm("add.rn.f32x2 %0,%1,%2;" : "=l"(d) : "l"(a), "l"(b)); return d;
}
__device__ __forceinline__ ull mul2(ull a, ull b) {
    ull d; asm("mul.rn.f32x2 %0,%1,%2;" : "=l"(d) : "l"(a), "l"(b)); return d;
}
__device__ __forceinline__ float ex2f(float x) {
    float y; asm("ex2.approx.f32 %0, %1;" : "=f"(y) : "f"(x)); return y;
}

// ---------------- weight repack ----------------
__global__ void repack_kernel(const float* __restrict__ wq, const float* __restrict__ wk,
                              const float* __restrict__ wv, const float* __restrict__ wo)
{
    int i = blockIdx.x * blockDim.x + threadIdx.x;
    if (i < 3 * 18432) {
        int t = i / 18432, r = i % 18432;
        int pos = r >> 5, co = r & 31;
        const float* w = (t == 0) ? wq : (t == 1) ? wk : wv;
        g_wqkv[i] = w[co * 576 + pos];
    } else if (i < 3 * 18432 + 18432) {
        int r = i - 3 * 18432;
        int pos = r >> 6, co = r & 63;
        g_wo[r] = wo[co * 288 + pos];
    }
}

// ---------------- QKV conv3x3 (64 -> 32), z = t*2 + co-half, packed f32x2 -----------
__global__ __launch_bounds__(128) void conv_qkv_kernel(
    const float* __restrict__ x,
    const float* __restrict__ bq, const float* __restrict__ bk, const float* __restrict__ bv)
{
    extern __shared__ float sm[];
    float* sx = sm;               // 64*10*18 = 11520 floats
    float* sw = sm + 11520;       // 576*16   = 9216 floats
    const int t = blockIdx.z >> 1, half = blockIdx.z & 1;
    const int y0 = blockIdx.y * 8, x0 = blockIdx.x * 16;
    const int tid = threadIdx.x;

    for (int idx = tid; idx < 11520; idx += 128) {
        int ci = idx / 180, rem = idx % 180;
        int ry = rem / 18, rx = rem % 18;
        int gy = y0 + ry - 1, gx = x0 + rx - 1;
        float v = 0.f;
        if (gy >= 0 && gy < HH && gx >= 0 && gx < WW) v = x[ci * HW + gy * WW + gx];
        sx[idx] = v;
    }
    {
        const float* wsrc = g_wqkv + t * 18432 + half * 16;
        for (int idx = tid; idx < 2304; idx += 128) {
            int pos = idx >> 2, q = idx & 3;
            float4 w4 = *(const float4*)(wsrc + pos * 32 + q * 4);
            *(float4*)&sw[pos * 16 + q * 4] = w4;
        }
    }
    __syncthreads();

    const int ty = tid >> 4, tx = tid & 15;
    const float* bias = (t == 0) ? bq : (t == 1) ? bk : bv;
    ull acc2[8];
    #pragma unroll
    for (int c = 0; c < 8; c++) acc2[c] = pk2(bias[half * 16 + 2*c], bias[half * 16 + 2*c + 1]);

    for (int ci = 0; ci < 64; ci++) {
        #pragma unroll
        for (int ky = 0; ky < 3; ky++) {
            #pragma unroll
            for (int kx = 0; kx < 3; kx++) {
                float xv = sx[(ci * 10 + ty + ky) * 18 + tx + kx];
                ull xv2 = pk2(xv, xv);
                const ulonglong2* wr = (const ulonglong2*)&sw[(ci * 9 + ky * 3 + kx) * 16];
                #pragma unroll
                for (int jj = 0; jj < 4; jj++) {
                    ulonglong2 w = wr[jj];
                    acc2[2*jj]   = fma2(xv2, w.x, acc2[2*jj]);
                    acc2[2*jj+1] = fma2(xv2, w.y, acc2[2*jj+1]);
                }
            }
        }
    }
    const int y = y0 + ty, xx = x0 + tx;
    float av[16];
    #pragma unroll
    for (int c = 0; c < 8; c++) upk2(av[2*c], av[2*c+1], acc2[c]);
    if (t == 0) {
        #pragma unroll
        for (int c = 0; c < 16; c++)
            g_qs[(half * 16 + c) * HW + y * WW + xx] = av[c] * LOG2E_HALF;
    } else {
        float* dst = (t == 1) ? g_kp : g_vp;
        #pragma unroll
        for (int c = 0; c < 16; c++)
            dst[((half * 16 + c) * 144 + y + 8) * 64 + (xx + 8)] = av[c];
    }
}

// ---------------- block-local attention, 3-way split-KV, MUFU ex2, 256 thr ----------
// grid (6 q-chunks, 16 blocks, 3 kv-thirds); 256 threads x 2 queries = 512 q/CTA.
// smem: component-sliced third-K/V: 8 * 1920 floats = 61440 bytes -> 3 CTAs/SM,
// 24 warps/SM = 6 warps/SMSP for rt-3 banked FFMA2 stall coverage.
__global__ __launch_bounds__(256, 3) void attn_kernel()
{
    extern __shared__ float sk[];
    const int n = blockIdx.y;
    const int s = blockIdx.z;
    const int h = n >> 1, j = n & 1;
    const int tid = threadIdx.x;

    // Stage one third of the flanged K/V (exact as_strided flat map):
    // flat = h*24576 + d*6144 + (s*48 + row)*48 + j*24 + m1
    {
        const int kbase = h * 24576 + j * 24 + s * 2304;
        for (int it = tid; it < MLEN; it += 256) {            // 4 comps * 48 rows * 10 vec4
            int c = it / 480, rem = it % 480;
            int row = rem / 10, v4 = rem % 10;
            int m = row * 40 + v4 * 4;
            int g = kbase + c * 6144 + row * 48 + v4 * 4;
            *(float4*)&sk[c * MLEN + m]          = *(const float4*)&g_kp[g];
            *(float4*)&sk[4*MLEN + c * MLEN + m] = *(const float4*)&g_vp[g];
        }
    }
    __syncthreads();

    const int qA = blockIdx.x * 512 + tid;
    const int qB = qA + 256;
    const int yA = qA / 24, xA = qA - yA * 24;
    const int yB = qB / 24, xB = qB - yB * 24;
    const int aA = yA * WW + j * 24 + xA;
    const int aB = yB * WW + j * 24 + xB;
    const int cb = h * 4 * HW;

    const ull qa0 = pk2(g_qs[cb + aA],        g_qs[cb + aA]);
    const ull qa1 = pk2(g_qs[cb + HW + aA],   g_qs[cb + HW + aA]);
    const ull qa2 = pk2(g_qs[cb + 2*HW + aA], g_qs[cb + 2*HW + aA]);
    const ull qa3 = pk2(g_qs[cb + 3*HW + aA], g_qs[cb + 3*HW + aA]);
    const ull qb0 = pk2(g_qs[cb + aB],        g_qs[cb + aB]);
    const ull qb1 = pk2(g_qs[cb + HW + aB],   g_qs[cb + HW + aB]);
    const ull qb2 = pk2(g_qs[cb + 2*HW + aB], g_qs[cb + 2*HW + aB]);
    const ull qb3 = pk2(g_qs[cb + 3*HW + aB], g_qs[cb + 3*HW + aB]);

    ull denA = 0, aAx = 0, aAy = 0, aAz = 0, aAw = 0;
    ull denB = 0, aBx = 0, aBy = 0, aBz = 0, aBw = 0;

    // 9 FFMA2 on the FMA pipe + 2 ex2 on MUFU per qstep (2 kv elements, 1 query)
    auto qstep = [&](ull q0, ull q1, ull q2, ull q3,
                     ull kx, ull ky, ull kz, ull kw,
                     ull vx, ull vy, ull vz, ull vw,
                     ull& den, ull& ax, ull& ay, ull& az, ull& aw)
    {
        ull s2 = fma2(q3, kw, fma2(q2, kz, fma2(q1, ky, mul2(q0, kx))));
        float sl, sh;
        upk2(sl, sh, s2);                 // free (register-pair aliasing)
        float el = ex2f(sl);              // MUFU
        float eh = ex2f(sh);              // MUFU
        ull e2 = pk2(el, eh);             // free
        den = add2(den, e2);
        ax = fma2(e2, vx, ax); ay = fma2(e2, vy, ay);
        az = fma2(e2, vz, az); aw = fma2(e2, vw, aw);
    };

    const float* skx = sk;
    const float* sky = sk + MLEN;
    const float* skz = sk + 2*MLEN;
    const float* skw = sk + 3*MLEN;
    const float* svx = sk + 4*MLEN;
    const float* svy = sk + 5*MLEN;
    const float* svz = sk + 6*MLEN;
    const float* svw = sk + 7*MLEN;

    for (int m = 0; m < MLEN; m += 4) {
        ulonglong2 kx = *(const ulonglong2*)(skx + m);
        ulonglong2 ky = *(const ulonglong2*)(sky + m);
        ulonglong2 kz = *(const ulonglong2*)(skz + m);
        ulonglong2 kw = *(const ulonglong2*)(skw + m);
        ulonglong2 vx = *(const ulonglong2*)(svx + m);
        ulonglong2 vy = *(const ulonglong2*)(svy + m);
        ulonglong2 vz = *(const ulonglong2*)(svz + m);
        ulonglong2 vw = *(const ulonglong2*)(svw + m);
        qstep(qa0,qa1,qa2,qa3, kx.x,ky.x,kz.x,kw.x, vx.x,vy.x,vz.x,vw.x, denA,aAx,aAy,aAz,aAw);
        qstep(qa0,qa1,qa2,qa3, kx.y,ky.y,kz.y,kw.y, vx.y,vy.y,vz.y,vw.y, denA,aAx,aAy,aAz,aAw);
        qstep(qb0,qb1,qb2,qb3, kx.x,ky.x,kz.x,kw.x, vx.x,vy.x,vz.x,vw.x, denB,aBx,aBy,aBz,aBw);
        qstep(qb0,qb1,qb2,qb3, kx.y,ky.y,kz.y,kw.y, vx.y,vy.y,vz.y,vw.y, denB,aBx,aBy,aBz,aBw);
    }

    float lo, hi;
    const int pbase = (s * 16 + n) * 4 * 3072;
    const int dbase = (s * 16 + n) * 3072;
    upk2(lo, hi, denA); g_pden[dbase + qA] = lo + hi;
    upk2(lo, hi, denB); g_pden[dbase + qB] = lo + hi;
    upk2(lo, hi, aAx); g_pnum[pbase + qA]          = lo + hi;
    upk2(lo, hi, aAy); g_pnum[pbase + 3072 + qA]   = lo + hi;
    upk2(lo, hi, aAz); g_pnum[pbase + 6144 + qA]   = lo + hi;
    upk2(lo, hi, aAw); g_pnum[pbase + 9216 + qA]   = lo + hi;
    upk2(lo, hi, aBx); g_pnum[pbase + qB]          = lo + hi;
    upk2(lo, hi, aBy); g_pnum[pbase + 3072 + qB]   = lo + hi;
    upk2(lo, hi, aBz); g_pnum[pbase + 6144 + qB]   = lo + hi;
    upk2(lo, hi, aBw); g_pnum[pbase + 9216 + qB]   = lo + hi;
}

// ---------------- combine split-KV partials into g_o --------------------------------
// Fine-grained: one thread per (n, c, q-quad) = 49152 threads (4x R8) for
// DRAM-latency hiding; den re-read per c is L2-hot, extra traffic ~1.8MB.
__global__ __launch_bounds__(128) void combine_kernel()
{
    int idx = blockIdx.x * 128 + threadIdx.x;      // 16*4*768 = 49152
    int n = idx / 3072, rem = idx - n * 3072;
    int c = rem / 768;
    int q = (rem - c * 768) * 4;
    int h = n >> 1, j = n & 1;
    int y = q / 24, x = q - y * 24;
    int a = y * WW + j * 24 + x;
    int cb = h * 4 * HW;

    float4 d0 = *(const float4*)&g_pden[n * 3072 + q];
    float4 d1 = *(const float4*)&g_pden[(16 + n) * 3072 + q];
    float4 d2 = *(const float4*)&g_pden[(32 + n) * 3072 + q];
    float4 p0 = *(const float4*)&g_pnum[(n * 4 + c) * 3072 + q];
    float4 p1 = *(const float4*)&g_pnum[((16 + n) * 4 + c) * 3072 + q];
    float4 p2 = *(const float4*)&g_pnum[((32 + n) * 4 + c) * 3072 + q];
    float4 o;
    o.x = (p0.x + p1.x + p2.x) / (d0.x + d1.x + d2.x);
    o.y = (p0.y + p1.y + p2.y) / (d0.y + d1.y + d2.y);
    o.z = (p0.z + p1.z + p2.z) / (d0.z + d1.z + d2.z);
    o.w = (p0.w + p1.w + p2.w) / (d0.w + d1.w + d2.w);
    *(float4*)&g_o[cb + c * HW + a] = o;
}

// ---------------- output conv3x3 (32 -> 64), z = co quarter, packed f32x2 -----------
__global__ __launch_bounds__(128) void conv_out_kernel(float* __restrict__ out)
{
    extern __shared__ float sm[];
    float* sx = sm;               // 32*10*18 = 5760 floats
    float* sw = sm + 5760;        // 288*16   = 4608 floats
    const int z  = blockIdx.z;
    const int y0 = blockIdx.y * 8, x0 = blockIdx.x * 16;
    const int tid = threadIdx.x;

    for (int idx = tid; idx < 5760; idx += 128) {
        int ci = idx / 180, rem = idx % 180;
        int ry = rem / 18, rx = rem % 18;
        int gy = y0 + ry - 1, gx = x0 + rx - 1;
        float v = 0.f;
        if (gy >= 0 && gy < HH && gx >= 0 && gx < WW) v = g_o[ci * HW + gy * WW + gx];
        sx[idx] = v;
    }
    for (int idx = tid; idx < 1152; idx += 128) {
        int pos = idx >> 2, q = idx & 3;
        float4 w4 = *(const float4*)(g_wo + pos * 64 + z * 16 + q * 4);
        *(float4*)&sw[pos * 16 + q * 4] = w4;
    }
    __syncthreads();

    const int ty = tid >> 4, tx = tid & 15;
    ull acc2[8];
    #pragma unroll
    for (int c = 0; c < 8; c++) acc2[c] = 0;

    for (int ci = 0; ci < 32; ci++) {
        #pragma unroll
        for (int ky = 0; ky < 3; ky++) {
            #pragma unroll
            for (int kx = 0; kx < 3; kx++) {
                float xv = sx[(ci * 10 + ty + ky) * 18 + tx + kx];
                ull xv2 = pk2(xv, xv);
                const ulonglong2* wr = (const ulonglong2*)&sw[(ci * 9 + ky * 3 + kx) * 16];
                #pragma unroll
                for (int jj = 0; jj < 4; jj++) {
                    ulonglong2 w = wr[jj];
                    acc2[2*jj]   = fma2(xv2, w.x, acc2[2*jj]);
                    acc2[2*jj+1] = fma2(xv2, w.y, acc2[2*jj+1]);
                }
            }
        }
    }
    const int y = y0 + ty, xx = x0 + tx;
    float av[16];
    #pragma unroll
    for (int c = 0; c < 8; c++) upk2(av[2*c], av[2*c+1], acc2[c]);
    #pragma unroll
    for (int c = 0; c < 16; c++)
        out[(z * 16 + c) * HW + y * WW + xx] = av[c];
}

// ---------------- launch ----------------
extern "C" void kernel_launch(void* const* d_in, const int* in_sizes, int n_in,
                              void* d_out, int out_size)
{
    const float* x  = (const float*)d_in[0];
    const float* wq = (const float*)d_in[1];
    const float* bq = (const float*)d_in[2];
    const float* wk = (const float*)d_in[3];
    const float* bk = (const float*)d_in[4];
    const float* wv = (const float*)d_in[5];
    const float* bv = (const float*)d_in[6];
    const float* wo = (const float*)d_in[7];
    float* out = (float*)d_out;

    cudaFuncSetAttribute(conv_qkv_kernel, cudaFuncAttributeMaxDynamicSharedMemorySize, 82944);
    cudaFuncSetAttribute(attn_kernel,     cudaFuncAttributeMaxDynamicSharedMemorySize, 61440);
    cudaFuncSetAttribute(conv_out_kernel, cudaFuncAttributeMaxDynamicSharedMemorySize, 41472);

    repack_kernel<<<(73728 + 255) / 256, 256>>>(wq, wk, wv, wo);
    conv_qkv_kernel<<<dim3(3, 16, 6), 128, 82944>>>(x, bq, bk, bv);
    attn_kernel<<<dim3(6, 16, 3), 256, 61440>>>();
    combine_kernel<<<384, 128>>>();
    conv_out_kernel<<<dim3(3, 16, 4), 128, 41472>>>(out);
}